// round 8
// baseline (speedup 1.0000x reference)
#include <cuda_runtime.h>
#include <cuda_bf16.h>
#include <cuda_fp16.h>
#include <cstdint>

// Problem constants
#define Tn   2048
#define Cdim 4096
#define NH   32
#define NKV  8
#define Dh   128
#define HDq  (NH*Dh)    // 4096
#define HDkv (NKV*Dh)   // 1024
#define HDA  (HDq + 2*HDkv)   // 6144 merged Q|K|V

// ---------------- scratch (device globals; no allocation) ----------------
__device__ __align__(256) __nv_bfloat16 g_xhi[Tn * Cdim];
__device__ __align__(256) __nv_bfloat16 g_xlo[Tn * Cdim];
__device__ __align__(256) __nv_bfloat16 g_qhi[(size_t)NH * Tn * Dh];
__device__ __align__(256) __nv_bfloat16 g_qlo[(size_t)NH * Tn * Dh];
__device__ __align__(256) __nv_bfloat16 g_khi[(size_t)NKV * Tn * Dh];
__device__ __align__(256) __nv_bfloat16 g_klo[(size_t)NKV * Tn * Dh];
__device__ __align__(256) __half       g_vh [(size_t)NKV * Tn * Dh];
__device__ __align__(256) __half       g_ybhi[Tn * Cdim];
__device__ __align__(256) __half       g_yblo[Tn * Cdim];
__device__ __align__(256) __nv_bfloat16 g_wahi[(size_t)HDA * Cdim];
__device__ __align__(256) __nv_bfloat16 g_walo[(size_t)HDA * Cdim];
__device__ __align__(256) __half       g_wohi[(size_t)Cdim * Cdim];

// ---------------- baseline-ISA helpers (sm_80+ PTX only) ----------------
__device__ __forceinline__ uint32_t smem_u32(const void* p) {
    uint32_t a;
    asm("{ .reg .u64 t; cvta.to.shared.u64 t, %1; cvt.u32.u64 %0, t; }" : "=r"(a) : "l"(p));
    return a;
}

#define CP_ASYNC16(sm, gp) \
    asm volatile("cp.async.cg.shared.global [%0], [%1], 16;" :: "r"(sm), "l"(gp) : "memory")
#define CP_COMMIT() asm volatile("cp.async.commit_group;" ::: "memory")
#define CP_WAIT(n)  asm volatile("cp.async.wait_group %0;" :: "n"(n) : "memory")

__device__ __forceinline__ void ldsm4(uint32_t* r, uint32_t addr) {
    asm volatile("ldmatrix.sync.aligned.m8n8.x4.shared.b16 {%0,%1,%2,%3}, [%4];"
        : "=r"(r[0]), "=r"(r[1]), "=r"(r[2]), "=r"(r[3]) : "r"(addr));
}
__device__ __forceinline__ void ldsm4t(uint32_t* r, uint32_t addr) {
    asm volatile("ldmatrix.sync.aligned.m8n8.x4.trans.shared.b16 {%0,%1,%2,%3}, [%4];"
        : "=r"(r[0]), "=r"(r[1]), "=r"(r[2]), "=r"(r[3]) : "r"(addr));
}

__device__ __forceinline__ void mma_bf16(float* c, const uint32_t* a, const uint32_t* b) {
    asm volatile(
        "mma.sync.aligned.m16n8k16.row.col.f32.bf16.bf16.f32 "
        "{%0,%1,%2,%3}, {%4,%5,%6,%7}, {%8,%9}, {%0,%1,%2,%3};"
        : "+f"(c[0]), "+f"(c[1]), "+f"(c[2]), "+f"(c[3])
        : "r"(a[0]), "r"(a[1]), "r"(a[2]), "r"(a[3]), "r"(b[0]), "r"(b[1]));
}
__device__ __forceinline__ void mma_f16(float* c, const uint32_t* a, const uint32_t* b) {
    asm volatile(
        "mma.sync.aligned.m16n8k16.row.col.f32.f16.f16.f32 "
        "{%0,%1,%2,%3}, {%4,%5,%6,%7}, {%8,%9}, {%0,%1,%2,%3};"
        : "+f"(c[0]), "+f"(c[1]), "+f"(c[2]), "+f"(c[3])
        : "r"(a[0]), "r"(a[1]), "r"(a[2]), "r"(a[3]), "r"(b[0]), "r"(b[1]));
}

__device__ __forceinline__ void split2h(float a, float b, uint32_t& hi, uint32_t& lo) {
    __half2 H = __floats2half2_rn(a, b);
    float ra = a - __half2float(__low2half(H));
    float rb = b - __half2float(__high2half(H));
    __half2 L = __floats2half2_rn(ra, rb);
    hi = *reinterpret_cast<uint32_t*>(&H);
    lo = *reinterpret_cast<uint32_t*>(&L);
}
__device__ __forceinline__ void split2b(float a, float b, uint32_t& hi, uint32_t& lo) {
    __nv_bfloat16 ah = __float2bfloat16(a), bh = __float2bfloat16(b);
    __nv_bfloat162 H; H.x = ah; H.y = bh;
    __nv_bfloat162 L;
    L.x = __float2bfloat16(a - __bfloat162float(ah));
    L.y = __float2bfloat16(b - __bfloat162float(bh));
    hi = *reinterpret_cast<uint32_t*>(&H);
    lo = *reinterpret_cast<uint32_t*>(&L);
}

// ---------------- split x (fp32 -> hi/lo bf16) ----------------
__global__ void __launch_bounds__(256) split_kernel(
    const float* __restrict__ X, __nv_bfloat16* __restrict__ hi,
    __nv_bfloat16* __restrict__ lo)
{
    int idx = blockIdx.x * 256 + threadIdx.x;
    float v = X[idx];
    __nv_bfloat16 h = __float2bfloat16(v);
    hi[idx] = h;
    lo[idx] = __float2bfloat16(v - __bfloat162float(h));
}

// ---------------- transpose+split W [K,N] fp32 -> [N,K] hi/lo bf16 ----------------
__global__ void __launch_bounds__(256) tsplit_kernel(
    const float* __restrict__ W, __nv_bfloat16* __restrict__ Thi,
    __nv_bfloat16* __restrict__ Tlo, int K, int N)
{
    __shared__ float tile[32][33];
    int n0 = blockIdx.x * 32, k0 = blockIdx.y * 32;
    int tx = threadIdx.x & 31, ty = threadIdx.x >> 5;
#pragma unroll
    for (int j = 0; j < 4; j++)
        tile[ty + 8 * j][tx] = W[(size_t)(k0 + ty + 8 * j) * N + n0 + tx];
    __syncthreads();
#pragma unroll
    for (int j = 0; j < 4; j++) {
        int n = ty + 8 * j;
        float v = tile[tx][n];
        __nv_bfloat16 h = __float2bfloat16(v);
        __nv_bfloat16 l = __float2bfloat16(v - __bfloat162float(h));
        size_t o = (size_t)(n0 + n) * K + k0 + tx;
        Thi[o] = h;
        Tlo[o] = l;
    }
}

// ---------------- transpose W [K,N] fp32 -> [N,K] fp16 (hi only) ----------------
__global__ void __launch_bounds__(256) tsplit_h_kernel(
    const float* __restrict__ W, __half* __restrict__ Thi, int K, int N)
{
    __shared__ float tile[32][33];
    int n0 = blockIdx.x * 32, k0 = blockIdx.y * 32;
    int tx = threadIdx.x & 31, ty = threadIdx.x >> 5;
#pragma unroll
    for (int j = 0; j < 4; j++)
        tile[ty + 8 * j][tx] = W[(size_t)(k0 + ty + 8 * j) * N + n0 + tx];
    __syncthreads();
#pragma unroll
    for (int j = 0; j < 4; j++) {
        int n = ty + 8 * j;
        Thi[(size_t)(n0 + n) * K + k0 + tx] = __float2half(tile[tx][n]);
    }
}

// ---------------- GEMM common geometry ----------------
#define PITCH   80
#define T_A     10240                  // 128 rows * 80B

// ---------------- fused QKV GEMM + RoPE epilogue ----------------
// C-tile = A(hi/lo)[128,4096] * B(hi/lo)^T for one 128-col slab = one head.
// Epilogue: stage fp32 tile to smem, apply rope (q/k) or pass (v), emit planes.
#define T_STAGE (4 * T_A)
#define G_SMEM  (2 * T_STAGE)          // 81920 >= 128*132*4 = 67584 staging
#define SPITCH  132

__device__ __forceinline__ void g_load_pair(
    uint32_t sbase, const __nv_bfloat16* __restrict__ hi,
    const __nv_bfloat16* __restrict__ lo, int rbase, int kc, int K, int tid)
{
#pragma unroll
    for (int i = 0; i < 2; i++) {
        int s = tid + 256 * i;
        int row = s >> 2, part = s & 3;
        size_t go = (size_t)(rbase + row) * K + (size_t)kc * 32 + part * 8;
        uint32_t so = (uint32_t)(row * PITCH + part * 16);
        CP_ASYNC16(sbase + so, hi + go);
        CP_ASYNC16(sbase + T_A + so, lo + go);
    }
}

__global__ void __launch_bounds__(256, 2) tcgemm_qkv_kernel(
    const __nv_bfloat16* __restrict__ Ahi, const __nv_bfloat16* __restrict__ Alo,
    const __nv_bfloat16* __restrict__ Bhi, const __nv_bfloat16* __restrict__ Blo,
    const float* __restrict__ cosb, const float* __restrict__ sinb,
    float* __restrict__ outK, float* __restrict__ outV)
{
    extern __shared__ char smc[];
    const uint32_t sb0 = smem_u32(smc);
    const int tid  = threadIdx.x;
    const int lane = tid & 31;
    const int wid  = tid >> 5;
    const int wm   = wid & 1;
    const int wn   = wid >> 1;
    const int row0 = blockIdx.y * 128;
    const int col0 = blockIdx.x * 128;
    const int K = Cdim;

    float acc[4][4][4];
#pragma unroll
    for (int m = 0; m < 4; m++)
#pragma unroll
        for (int n = 0; n < 4; n++)
#pragma unroll
            for (int e = 0; e < 4; e++) acc[m][n][e] = 0.f;

    const uint32_t a_row = (uint32_t)(wm * 64 + (lane & 15));
    const uint32_t a_kb  = (uint32_t)((lane >> 4) * 16);
    const int bmat = lane >> 3, bwin = lane & 7;
    const uint32_t b_n  = (uint32_t)(wn * 32 + bwin + (bmat >> 1) * 8);
    const uint32_t b_kb = (uint32_t)((bmat & 1) * 16);

    const int nk = K >> 5;

    g_load_pair(sb0,           Ahi, Alo, row0, 0, K, tid);
    g_load_pair(sb0 + 2 * T_A, Bhi, Blo, col0, 0, K, tid);
    CP_COMMIT();

    for (int kc = 0; kc < nk; kc++) {
        uint32_t sb = sb0 + (uint32_t)(kc & 1) * T_STAGE;
        if (kc + 1 < nk) {
            uint32_t sb2 = sb0 + (uint32_t)((kc + 1) & 1) * T_STAGE;
            g_load_pair(sb2,           Ahi, Alo, row0, kc + 1, K, tid);
            g_load_pair(sb2 + 2 * T_A, Bhi, Blo, col0, kc + 1, K, tid);
            CP_COMMIT();
            CP_WAIT(1);
        } else {
            CP_WAIT(0);
        }
        __syncthreads();

        const uint32_t aB = sb + a_row * PITCH + a_kb;
        const uint32_t bB = sb + 2 * T_A + b_n * PITCH + b_kb;

#pragma unroll
        for (int ks = 0; ks < 2; ks++) {
            uint32_t ah[4][4], al[4][4], bh[2][4], bl[2][4];
#pragma unroll
            for (int m = 0; m < 4; m++) {
                ldsm4(ah[m], aB + (uint32_t)(m * 16 * PITCH) + ks * 32);
                ldsm4(al[m], aB + T_A + (uint32_t)(m * 16 * PITCH) + ks * 32);
            }
#pragma unroll
            for (int p = 0; p < 2; p++) {
                ldsm4(bh[p], bB + (uint32_t)(p * 16 * PITCH) + ks * 32);
                ldsm4(bl[p], bB + T_A + (uint32_t)(p * 16 * PITCH) + ks * 32);
            }
#pragma unroll
            for (int m = 0; m < 4; m++)
#pragma unroll
                for (int p = 0; p < 2; p++)
#pragma unroll
                    for (int h = 0; h < 2; h++) {
                        float* c = acc[m][p * 2 + h];
                        uint32_t bhh[2] = {bh[p][h * 2], bh[p][h * 2 + 1]};
                        uint32_t bll[2] = {bl[p][h * 2], bl[p][h * 2 + 1]};
                        mma_bf16(c, ah[m], bhh);
                        mma_bf16(c, ah[m], bll);
                        mma_bf16(c, al[m], bhh);
                    }
        }
        __syncthreads();
    }

    // ---- epilogue: stage fp32 tile to smem ----
    float* sst = reinterpret_cast<float*>(smc);
    const int g = lane >> 2, t4 = lane & 3;
#pragma unroll
    for (int m = 0; m < 4; m++) {
        int r = wm * 64 + m * 16 + g;
#pragma unroll
        for (int n = 0; n < 4; n++) {
            int c = wn * 32 + n * 8 + 2 * t4;
            *(float2*)&sst[r * SPITCH + c]       = make_float2(acc[m][n][0], acc[m][n][1]);
            *(float2*)&sst[(r + 8) * SPITCH + c] = make_float2(acc[m][n][2], acc[m][n][3]);
        }
    }
    __syncthreads();

    // ---- rope / convert + store: 16 iterations, 2 d-columns per thread ----
    const int head = col0 >> 7;              // 0..47
#pragma unroll
    for (int i = 0; i < 16; i++) {
        int idx = i * 512 + tid * 2;         // pair index *2
        int d = idx & 63;                    // even
        int r = idx >> 6;
        int t = row0 + r;
        float2 u1 = *(const float2*)&sst[r * SPITCH + d];
        float2 u2 = *(const float2*)&sst[r * SPITCH + d + 64];
        if (head < NH) {
            // ---- Q: rope -> bf16 hi/lo planes ----
            float2 c1 = *(const float2*)&cosb[t * Dh + d];
            float2 s1 = *(const float2*)&sinb[t * Dh + d];
            float2 c2 = *(const float2*)&cosb[t * Dh + d + 64];
            float2 s2 = *(const float2*)&sinb[t * Dh + d + 64];
            float y1a = u1.x * c1.x - u2.x * s1.x;
            float y1b = u1.y * c1.y - u2.y * s1.y;
            float y2a = u2.x * c2.x + u1.x * s2.x;
            float y2b = u2.y * c2.y + u1.y * s2.y;
            size_t o = ((size_t)head * Tn + t) * Dh + d;
            uint32_t h1, l1, h2, l2;
            split2b(y1a, y1b, h1, l1);
            split2b(y2a, y2b, h2, l2);
            *reinterpret_cast<uint32_t*>(g_qhi + o)      = h1;
            *reinterpret_cast<uint32_t*>(g_qlo + o)      = l1;
            *reinterpret_cast<uint32_t*>(g_qhi + o + 64) = h2;
            *reinterpret_cast<uint32_t*>(g_qlo + o + 64) = l2;
        } else if (head < NH + NKV) {
            // ---- K: rope -> fp32 out + bf16 hi/lo planes ----
            int kh = head - NH;
            float2 c1 = *(const float2*)&cosb[t * Dh + d];
            float2 s1 = *(const float2*)&sinb[t * Dh + d];
            float2 c2 = *(const float2*)&cosb[t * Dh + d + 64];
            float2 s2 = *(const float2*)&sinb[t * Dh + d + 64];
            float y1a = u1.x * c1.x - u2.x * s1.x;
            float y1b = u1.y * c1.y - u2.y * s1.y;
            float y2a = u2.x * c2.x + u1.x * s2.x;
            float y2b = u2.y * c2.y + u1.y * s2.y;
            size_t o = ((size_t)kh * Tn + t) * Dh + d;
            *(float2*)(outK + o)      = make_float2(y1a, y1b);
            *(float2*)(outK + o + 64) = make_float2(y2a, y2b);
            uint32_t h1, l1, h2, l2;
            split2b(y1a, y1b, h1, l1);
            split2b(y2a, y2b, h2, l2);
            *reinterpret_cast<uint32_t*>(g_khi + o)      = h1;
            *reinterpret_cast<uint32_t*>(g_klo + o)      = l1;
            *reinterpret_cast<uint32_t*>(g_khi + o + 64) = h2;
            *reinterpret_cast<uint32_t*>(g_klo + o + 64) = l2;
        } else {
            // ---- V: pass-through -> fp32 out + fp16 plane ----
            int kh = head - NH - NKV;
            size_t o = ((size_t)kh * Tn + t) * Dh + d;
            *(float2*)(outV + o)      = u1;
            *(float2*)(outV + o + 64) = u2;
            __half2 vh1 = __floats2half2_rn(u1.x, u1.y);
            __half2 vh2 = __floats2half2_rn(u2.x, u2.y);
            *reinterpret_cast<__half2*>(g_vh + o)      = vh1;
            *reinterpret_cast<__half2*>(g_vh + o + 64) = vh2;
        }
    }
}

// ---------------- fp16 2-MMA GEMM: C = (Ahi+Alo) * Bhi^T ----------------
#define T2_STAGE (3 * T_A)             // Ah, Al, Bh
#define G2_SMEM  (2 * T2_STAGE)        // 61440

__global__ void __launch_bounds__(256, 2) tcgemm2_kernel(
    const __half* __restrict__ Ahi, const __half* __restrict__ Alo,
    const __half* __restrict__ Bhi,
    float* __restrict__ C, int N, int K)
{
    extern __shared__ char smc[];
    const uint32_t sb0 = smem_u32(smc);
    const int tid  = threadIdx.x;
    const int lane = tid & 31;
    const int wid  = tid >> 5;
    const int wm   = wid & 1;
    const int wn   = wid >> 1;
    const int row0 = blockIdx.y * 128;
    const int col0 = blockIdx.x * 128;

    float acc[4][4][4];
#pragma unroll
    for (int m = 0; m < 4; m++)
#pragma unroll
        for (int n = 0; n < 4; n++)
#pragma unroll
            for (int e = 0; e < 4; e++) acc[m][n][e] = 0.f;

    const uint32_t a_row = (uint32_t)(wm * 64 + (lane & 15));
    const uint32_t a_kb  = (uint32_t)((lane >> 4) * 16);
    const int bmat = lane >> 3, bwin = lane & 7;
    const uint32_t b_n  = (uint32_t)(wn * 32 + bwin + (bmat >> 1) * 8);
    const uint32_t b_kb = (uint32_t)((bmat & 1) * 16);

    const int nk = K >> 5;

    auto load_stage = [&](uint32_t sb, int kc) {
#pragma unroll
        for (int i = 0; i < 2; i++) {
            int s = tid + 256 * i;
            int row = s >> 2, part = s & 3;
            size_t goA = (size_t)(row0 + row) * K + (size_t)kc * 32 + part * 8;
            size_t goB = (size_t)(col0 + row) * K + (size_t)kc * 32 + part * 8;
            uint32_t so = (uint32_t)(row * PITCH + part * 16);
            CP_ASYNC16(sb + so,           Ahi + goA);
            CP_ASYNC16(sb + T_A + so,     Alo + goA);
            CP_ASYNC16(sb + 2 * T_A + so, Bhi + goB);
        }
    };

    load_stage(sb0, 0);
    CP_COMMIT();

    for (int kc = 0; kc < nk; kc++) {
        uint32_t sb = sb0 + (uint32_t)(kc & 1) * T2_STAGE;
        if (kc + 1 < nk) {
            load_stage(sb0 + (uint32_t)((kc + 1) & 1) * T2_STAGE, kc + 1);
            CP_COMMIT();
            CP_WAIT(1);
        } else {
            CP_WAIT(0);
        }
        __syncthreads();

        const uint32_t aB = sb + a_row * PITCH + a_kb;
        const uint32_t bB = sb + 2 * T_A + b_n * PITCH + b_kb;

#pragma unroll
        for (int ks = 0; ks < 2; ks++) {
            uint32_t ah[4][4], al[4][4], bh[2][4];
#pragma unroll
            for (int m = 0; m < 4; m++) {
                ldsm4(ah[m], aB + (uint32_t)(m * 16 * PITCH) + ks * 32);
                ldsm4(al[m], aB + T_A + (uint32_t)(m * 16 * PITCH) + ks * 32);
            }
#pragma unroll
            for (int p = 0; p < 2; p++)
                ldsm4(bh[p], bB + (uint32_t)(p * 16 * PITCH) + ks * 32);
#pragma unroll
            for (int m = 0; m < 4; m++)
#pragma unroll
                for (int p = 0; p < 2; p++)
#pragma unroll
                    for (int h = 0; h < 2; h++) {
                        float* c = acc[m][p * 2 + h];
                        uint32_t bhh[2] = {bh[p][h * 2], bh[p][h * 2 + 1]};
                        mma_f16(c, ah[m], bhh);
                        mma_f16(c, al[m], bhh);
                    }
        }
        __syncthreads();
    }

    const int g = lane >> 2, t = lane & 3;
#pragma unroll
    for (int m = 0; m < 4; m++) {
        int r0 = row0 + wm * 64 + m * 16 + g;
#pragma unroll
        for (int n = 0; n < 4; n++) {
            int c = col0 + wn * 32 + n * 8 + 2 * t;
            *(float2*)&C[(size_t)r0 * N + c] = make_float2(acc[m][n][0], acc[m][n][1]);
            *(float2*)&C[(size_t)(r0 + 8) * N + c] = make_float2(acc[m][n][2], acc[m][n][3]);
        }
    }
}

// ---------------- flash attention (QK: bf16 3-MMA, PV: fp16 2-MMA) ----------------
// BM=128, BN=64. 8 warps, each owns 16 rows full width. grid (16, NH), 256 thr.
// 3-stage KV pipeline.
#define FP272   272
#define QTILE   (128 * FP272)          // 34816
#define KTILE   (64 * FP272)           // 17408
#define FSTAGE  (3 * KTILE)            // Kh, Kl, Vh = 52224
#define F_SMEM  (2 * QTILE + 3 * FSTAGE)  // 226304

__device__ __forceinline__ void f_load_kv(
    uint32_t st, const __nv_bfloat16* __restrict__ kh,
    const __nv_bfloat16* __restrict__ kl, const __half* __restrict__ vh, int tid)
{
#pragma unroll
    for (int i = 0; i < 4; i++) {
        int s = tid + 256 * i;             // 1024 chunks of 16B per tile
        int r = s >> 4, c = s & 15;
        uint32_t so = (uint32_t)(r * FP272 + c * 16);
        size_t go = (size_t)r * Dh + c * 8;
        CP_ASYNC16(st + so,             kh + go);
        CP_ASYNC16(st + KTILE + so,     kl + go);
        CP_ASYNC16(st + 2 * KTILE + so, vh + go);
    }
}

__global__ void __launch_bounds__(256) flash_mma_kernel(
    __half* __restrict__ ybhi, __half* __restrict__ yblo)
{
    extern __shared__ char smc[];
    const uint32_t sb = smem_u32(smc);
    const int tid = threadIdx.x, lane = tid & 31, w = tid >> 5;
    const int h  = blockIdx.y;
    const int qi = (int)gridDim.x - 1 - (int)blockIdx.x;   // big tiles first
    const int q0 = qi * 128;
    const int kvh = h >> 2;
    const int nb = 2 * qi + 2;

    const uint32_t sQh = sb, sQl = sb + QTILE;
    const uint32_t sKV = sb + 2 * QTILE;

    const uint32_t aQoff = (uint32_t)((16 * w + (lane & 15)) * FP272 + (lane >> 4) * 16);
    const int bmat = lane >> 3, bwin = lane & 7;
    const uint32_t bKoff = (uint32_t)((bwin + ((bmat >> 1) << 3)) * FP272 + ((bmat & 1) << 4));
    const uint32_t bVoff = (uint32_t)((lane & 15) * FP272 + ((lane >> 4) << 4));

    const __nv_bfloat16* gKh = g_khi + (size_t)kvh * Tn * Dh;
    const __nv_bfloat16* gKl = g_klo + (size_t)kvh * Tn * Dh;
    const __half*        gVh = g_vh  + (size_t)kvh * Tn * Dh;

    // prologue: Q + KV0 (group 0), KV1 (group 1; nb >= 2 always)
    {
        const __nv_bfloat16* gqh = g_qhi + ((size_t)h * Tn + q0) * Dh;
        const __nv_bfloat16* gql = g_qlo + ((size_t)h * Tn + q0) * Dh;
#pragma unroll
        for (int i = 0; i < 8; i++) {
            int s = tid + 256 * i;
            int r = s >> 4, c = s & 15;
            uint32_t so = (uint32_t)(r * FP272 + c * 16);
            size_t go = (size_t)r * Dh + c * 8;
            CP_ASYNC16(sQh + so, gqh + go);
            CP_ASYNC16(sQl + so, gql + go);
        }
        f_load_kv(sKV, gKh, gKl, gVh, tid);
        CP_COMMIT();
        f_load_kv(sKV + FSTAGE, gKh + (size_t)64 * Dh, gKl + (size_t)64 * Dh,
                  gVh + (size_t)64 * Dh, tid);
        CP_COMMIT();
    }

    CP_WAIT(1);
    __syncthreads();
    uint32_t qh_f[8][4], ql_f[8][4];
#pragma unroll
    for (int ks = 0; ks < 8; ks++) {
        ldsm4(qh_f[ks], sQh + aQoff + ks * 32);
        ldsm4(ql_f[ks], sQl + aQoff + ks * 32);
    }

    float o[16][4];
#pragma unroll
    for (int dt = 0; dt < 16; dt++)
#pragma unroll
        for (int e = 0; e < 4; e++) o[dt][e] = 0.f;
    float m0 = -1e30f, m1 = -1e30f, l0 = 0.f, l1 = 0.f;

    const int row_lo = q0 + 16 * w + (lane >> 2);
    const int row_hi = row_lo + 8;

    for (int j = 0; j < nb; j++) {
        if (j > 0) {
            if (j + 1 < nb) CP_WAIT(1); else CP_WAIT(0);
            __syncthreads();
        }
        if (j + 2 < nb) {
            size_t kb = (size_t)(j + 2) * 64;
            f_load_kv(sKV + (uint32_t)((j + 2) % 3) * FSTAGE,
                      gKh + kb * Dh, gKl + kb * Dh, gVh + kb * Dh, tid);
            CP_COMMIT();
        }

        const uint32_t stg = sKV + (uint32_t)(j % 3) * FSTAGE;
        const int kb0 = j * 64;
        const bool active = (q0 + 16 * w + 15) >= kb0;

        if (active) {
            float sc[8][4];
#pragma unroll
            for (int nt = 0; nt < 8; nt++)
#pragma unroll
                for (int e = 0; e < 4; e++) sc[nt][e] = 0.f;

#pragma unroll
            for (int ks = 0; ks < 8; ks++) {
#pragma unroll
                for (int p = 0; p < 4; p++) {
                    uint32_t khf[4], klf[4];
                    uint32_t ka = stg + bKoff + (uint32_t)(p * 16 * FP272) + ks * 32;
                    ldsm4(khf, ka);
                    ldsm4(klf, ka + KTILE);
#pragma unroll
                    for (int hh = 0; hh < 2; hh++) {
                        float* c = sc[p * 2 + hh];
                        uint32_t bh2[2] = {khf[hh * 2], khf[hh * 2 + 1]};
                        uint32_t bl2[2] = {klf[hh * 2], klf[hh * 2 + 1]};
                        mma_bf16(c, qh_f[ks], bh2);
                        mma_bf16(c, qh_f[ks], bl2);
                        mma_bf16(c, ql_f[ks], bh2);
                    }
                }
            }

            if (kb0 + 63 > row_lo) {
#pragma unroll
                for (int nt = 0; nt < 8; nt++) {
                    int col = kb0 + nt * 8 + 2 * (lane & 3);
                    if (col > row_lo)     sc[nt][0] = -1e30f;
                    if (col + 1 > row_lo) sc[nt][1] = -1e30f;
                    if (col > row_hi)     sc[nt][2] = -1e30f;
                    if (col + 1 > row_hi) sc[nt][3] = -1e30f;
                }
            }

            float ml0 = -1e30f, ml1 = -1e30f;
#pragma unroll
            for (int nt = 0; nt < 8; nt++) {
                ml0 = fmaxf(ml0, fmaxf(sc[nt][0], sc[nt][1]));
                ml1 = fmaxf(ml1, fmaxf(sc[nt][2], sc[nt][3]));
            }
            ml0 = fmaxf(ml0, __shfl_xor_sync(0xffffffffu, ml0, 1));
            ml0 = fmaxf(ml0, __shfl_xor_sync(0xffffffffu, ml0, 2));
            ml1 = fmaxf(ml1, __shfl_xor_sync(0xffffffffu, ml1, 1));
            ml1 = fmaxf(ml1, __shfl_xor_sync(0xffffffffu, ml1, 2));
            float mn0 = fmaxf(m0, ml0), mn1 = fmaxf(m1, ml1);
            float es0 = __expf(m0 - mn0), es1 = __expf(m1 - mn1);
            float ls0 = 0.f, ls1 = 0.f;
#pragma unroll
            for (int nt = 0; nt < 8; nt++) {
                sc[nt][0] = __expf(sc[nt][0] - mn0);
                sc[nt][1] = __expf(sc[nt][1] - mn0);
                sc[nt][2] = __expf(sc[nt][2] - mn1);
                sc[nt][3] = __expf(sc[nt][3] - mn1);
                ls0 += sc[nt][0] + sc[nt][1];
                ls1 += sc[nt][2] + sc[nt][3];
            }
            ls0 += __shfl_xor_sync(0xffffffffu, ls0, 1);
            ls0 += __shfl_xor_sync(0xffffffffu, ls0, 2);
            ls1 += __shfl_xor_sync(0xffffffffu, ls1, 1);
            ls1 += __shfl_xor_sync(0xffffffffu, ls1, 2);
            l0 = l0 * es0 + ls0;  m0 = mn0;
            l1 = l1 * es1 + ls1;  m1 = mn1;
#pragma unroll
            for (int dt = 0; dt < 16; dt++) {
                o[dt][0] *= es0;  o[dt][1] *= es0;
                o[dt][2] *= es1;  o[dt][3] *= es1;
            }

#pragma unroll
            for (int j2 = 0; j2 < 4; j2++) {
                uint32_t ph[4], pl[4];
                split2h(sc[2 * j2][0],     sc[2 * j2][1],     ph[0], pl[0]);
                split2h(sc[2 * j2][2],     sc[2 * j2][3],     ph[1], pl[1]);
                split2h(sc[2 * j2 + 1][0], sc[2 * j2 + 1][1], ph[2], pl[2]);
                split2h(sc[2 * j2 + 1][2], sc[2 * j2 + 1][3], ph[3], pl[3]);
#pragma unroll
                for (int dt2 = 0; dt2 < 8; dt2++) {
                    uint32_t vhf[4];
                    uint32_t va = stg + 2 * KTILE + bVoff +
                                  (uint32_t)(j2 * 16 * FP272) + (uint32_t)(dt2 * 32);
                    ldsm4t(vhf, va);
#pragma unroll
                    for (int hf = 0; hf < 2; hf++) {
                        float* c = o[dt2 * 2 + hf];
                        uint32_t bh2[2] = {vhf[hf * 2], vhf[hf * 2 + 1]};
                        mma_f16(c, ph, bh2);
                        mma_f16(c, pl, bh2);
                    }
                }
            }
        }
    }

    float inv0 = 1.f / l0, inv1 = 1.f / l1;
#pragma unroll
    for (int dt = 0; dt < 16; dt++) {
        int d = dt * 8 + 2 * (lane & 3);
        size_t o0 = (size_t)row_lo * Cdim + h * Dh + d;
        size_t o1 = (size_t)row_hi * Cdim + h * Dh + d;
        uint32_t hi0, lo0, hi1, lo1;
        split2h(o[dt][0] * inv0, o[dt][1] * inv0, hi0, lo0);
        split2h(o[dt][2] * inv1, o[dt][3] * inv1, hi1, lo1);
        *reinterpret_cast<uint32_t*>(ybhi + o0) = hi0;
        *reinterpret_cast<uint32_t*>(yblo + o0) = lo0;
        *reinterpret_cast<uint32_t*>(ybhi + o1) = hi1;
        *reinterpret_cast<uint32_t*>(yblo + o1) = lo1;
    }
}

// ---------------- launch ----------------
extern "C" void kernel_launch(void* const* d_in, const int* in_sizes, int n_in,
                              void* d_out, int out_size)
{
    const float* x    = (const float*)d_in[0];
    const float* Wq   = (const float*)d_in[1];
    const float* Wk   = (const float*)d_in[2];
    const float* Wv   = (const float*)d_in[3];
    const float* Wo   = (const float*)d_in[4];
    const float* cosb = (const float*)d_in[5];
    const float* sinb = (const float*)d_in[6];
    // d_in[7] = mask (reproduced exactly by causal structure; unused)

    float* out  = (float*)d_out;
    float* outY = out;
    float* outK = out + (size_t)Tn * Cdim;
    float* outV = outK + (size_t)NKV * Tn * Dh;

    __nv_bfloat16 *xhi, *xlo, *wahi, *walo;
    __half *ybhi, *yblo, *wohi;
    cudaGetSymbolAddress((void**)&xhi, g_xhi);
    cudaGetSymbolAddress((void**)&xlo, g_xlo);
    cudaGetSymbolAddress((void**)&wahi, g_wahi);
    cudaGetSymbolAddress((void**)&walo, g_walo);
    cudaGetSymbolAddress((void**)&ybhi, g_ybhi);
    cudaGetSymbolAddress((void**)&yblo, g_yblo);
    cudaGetSymbolAddress((void**)&wohi, g_wohi);

    cudaFuncSetAttribute(tcgemm_qkv_kernel, cudaFuncAttributeMaxDynamicSharedMemorySize,
                         G_SMEM);
    cudaFuncSetAttribute(tcgemm2_kernel, cudaFuncAttributeMaxDynamicSharedMemorySize,
                         G2_SMEM);
    cudaFuncSetAttribute(flash_mma_kernel, cudaFuncAttributeMaxDynamicSharedMemorySize,
                         F_SMEM);

    // 0. split/transpose prep (weights into one merged [6144, 4096] array)
    split_kernel<<<(Tn * Cdim) / 256, 256>>>(x, xhi, xlo);
    tsplit_kernel<<<dim3(HDq / 32, Cdim / 32), 256>>>(Wq, wahi, walo, Cdim, HDq);
    tsplit_kernel<<<dim3(HDkv / 32, Cdim / 32), 256>>>(
        Wk, wahi + (size_t)HDq * Cdim, walo + (size_t)HDq * Cdim, Cdim, HDkv);
    tsplit_kernel<<<dim3(HDkv / 32, Cdim / 32), 256>>>(
        Wv, wahi + (size_t)(HDq + HDkv) * Cdim, walo + (size_t)(HDq + HDkv) * Cdim,
        Cdim, HDkv);
    tsplit_h_kernel<<<dim3(Cdim / 32, Cdim / 32), 256>>>(Wo, wohi, Cdim, Cdim);

    // 1. merged QKV projection + fused RoPE epilogue (one launch, N=6144)
    tcgemm_qkv_kernel<<<dim3(HDA / 128, Tn / 128), 256, G_SMEM>>>(
        xhi, xlo, wahi, walo, cosb, sinb, outK, outV);

    // 2. causal flash attention (tensor cores, 3-stage KV pipeline)
    flash_mma_kernel<<<dim3(Tn / 128, NH), 256, F_SMEM>>>(ybhi, yblo);

    // 3. output projection (fp16 2-MMA)
    tcgemm2_kernel<<<dim3(Cdim / 128, Tn / 128), 256, G2_SMEM>>>(
        ybhi, yblo, wohi, outY, Cdim, Cdim);
}

// round 9
// speedup vs baseline: 1.0552x; 1.0552x over previous
#include <cuda_runtime.h>
#include <cuda_bf16.h>
#include <cuda_fp16.h>
#include <cstdint>

// Problem constants
#define Tn   2048
#define Cdim 4096
#define NH   32
#define NKV  8
#define Dh   128
#define HDq  (NH*Dh)    // 4096
#define HDkv (NKV*Dh)   // 1024
#define HDA  (HDq + 2*HDkv)   // 6144 merged Q|K|V

// ---------------- scratch (device globals; no allocation) ----------------
__device__ __align__(256) float g_tqkv[(size_t)Tn * HDA];

__device__ __align__(256) __nv_bfloat16 g_xhi[Tn * Cdim];
__device__ __align__(256) __nv_bfloat16 g_xlo[Tn * Cdim];
__device__ __align__(256) __nv_bfloat16 g_qhi[(size_t)NH * Tn * Dh];
__device__ __align__(256) __nv_bfloat16 g_qlo[(size_t)NH * Tn * Dh];
__device__ __align__(256) __nv_bfloat16 g_khi[(size_t)NKV * Tn * Dh];
__device__ __align__(256) __nv_bfloat16 g_klo[(size_t)NKV * Tn * Dh];
__device__ __align__(256) __half       g_vh [(size_t)NKV * Tn * Dh];
__device__ __align__(256) __half       g_ybhi[Tn * Cdim];
__device__ __align__(256) __half       g_yblo[Tn * Cdim];
__device__ __align__(256) __nv_bfloat16 g_wahi[(size_t)HDA * Cdim];
__device__ __align__(256) __nv_bfloat16 g_walo[(size_t)HDA * Cdim];
__device__ __align__(256) __half       g_wohi[(size_t)Cdim * Cdim];

// ---------------- baseline-ISA helpers (sm_80+ PTX only) ----------------
__device__ __forceinline__ uint32_t smem_u32(const void* p) {
    uint32_t a;
    asm("{ .reg .u64 t; cvta.to.shared.u64 t, %1; cvt.u32.u64 %0, t; }" : "=r"(a) : "l"(p));
    return a;
}

#define CP_ASYNC16(sm, gp) \
    asm volatile("cp.async.cg.shared.global [%0], [%1], 16;" :: "r"(sm), "l"(gp) : "memory")
#define CP_COMMIT() asm volatile("cp.async.commit_group;" ::: "memory")
#define CP_WAIT(n)  asm volatile("cp.async.wait_group %0;" :: "n"(n) : "memory")

__device__ __forceinline__ void ldsm4(uint32_t* r, uint32_t addr) {
    asm volatile("ldmatrix.sync.aligned.m8n8.x4.shared.b16 {%0,%1,%2,%3}, [%4];"
        : "=r"(r[0]), "=r"(r[1]), "=r"(r[2]), "=r"(r[3]) : "r"(addr));
}
__device__ __forceinline__ void ldsm4t(uint32_t* r, uint32_t addr) {
    asm volatile("ldmatrix.sync.aligned.m8n8.x4.trans.shared.b16 {%0,%1,%2,%3}, [%4];"
        : "=r"(r[0]), "=r"(r[1]), "=r"(r[2]), "=r"(r[3]) : "r"(addr));
}

__device__ __forceinline__ void mma_bf16(float* c, const uint32_t* a, const uint32_t* b) {
    asm volatile(
        "mma.sync.aligned.m16n8k16.row.col.f32.bf16.bf16.f32 "
        "{%0,%1,%2,%3}, {%4,%5,%6,%7}, {%8,%9}, {%0,%1,%2,%3};"
        : "+f"(c[0]), "+f"(c[1]), "+f"(c[2]), "+f"(c[3])
        : "r"(a[0]), "r"(a[1]), "r"(a[2]), "r"(a[3]), "r"(b[0]), "r"(b[1]));
}
__device__ __forceinline__ void mma_f16(float* c, const uint32_t* a, const uint32_t* b) {
    asm volatile(
        "mma.sync.aligned.m16n8k16.row.col.f32.f16.f16.f32 "
        "{%0,%1,%2,%3}, {%4,%5,%6,%7}, {%8,%9}, {%0,%1,%2,%3};"
        : "+f"(c[0]), "+f"(c[1]), "+f"(c[2]), "+f"(c[3])
        : "r"(a[0]), "r"(a[1]), "r"(a[2]), "r"(a[3]), "r"(b[0]), "r"(b[1]));
}

__device__ __forceinline__ void split2h(float a, float b, uint32_t& hi, uint32_t& lo) {
    __half2 H = __floats2half2_rn(a, b);
    float ra = a - __half2float(__low2half(H));
    float rb = b - __half2float(__high2half(H));
    __half2 L = __floats2half2_rn(ra, rb);
    hi = *reinterpret_cast<uint32_t*>(&H);
    lo = *reinterpret_cast<uint32_t*>(&L);
}

// ---------------- merged prep: x split + W transposes, one launch ----------------
// block ranges:
//   [0, 32768)              : x fp32 -> hi/lo bf16 (elementwise)
//   [32768, 49152)          : Wq  tsplit -> wahi/walo @0          (N=4096)
//   [49152, 53248)          : Wk  tsplit -> wahi/walo @HDq*C      (N=1024)
//   [53248, 57344)          : Wv  tsplit -> wahi/walo @(HDq+HDkv)*C (N=1024)
//   [57344, 73728)          : Wo  fp16 transpose -> wohi          (N=4096)
#define PREP_X   32768
#define PREP_WQ  (PREP_X + 16384)
#define PREP_WK  (PREP_WQ + 4096)
#define PREP_WV  (PREP_WK + 4096)
#define PREP_END (PREP_WV + 16384)

__global__ void __launch_bounds__(256) prep_kernel(
    const float* __restrict__ x,
    const float* __restrict__ Wq, const float* __restrict__ Wk,
    const float* __restrict__ Wv, const float* __restrict__ Wo)
{
    __shared__ float tile[32][33];
    const int bid = blockIdx.x;
    if (bid < PREP_X) {
        int idx = bid * 256 + threadIdx.x;
        float v = x[idx];
        __nv_bfloat16 h = __float2bfloat16(v);
        g_xhi[idx] = h;
        g_xlo[idx] = __float2bfloat16(v - __bfloat162float(h));
        return;
    }
    const float* W;
    __nv_bfloat16 *Thi, *Tlo;
    int N, rel;
    bool is_half = false;
    if (bid < PREP_WQ)      { rel = bid - PREP_X;  W = Wq; N = HDq;
                              Thi = g_wahi; Tlo = g_walo; }
    else if (bid < PREP_WK) { rel = bid - PREP_WQ; W = Wk; N = HDkv;
                              Thi = g_wahi + (size_t)HDq * Cdim;
                              Tlo = g_walo + (size_t)HDq * Cdim; }
    else if (bid < PREP_WV) { rel = bid - PREP_WK; W = Wv; N = HDkv;
                              Thi = g_wahi + (size_t)(HDq + HDkv) * Cdim;
                              Tlo = g_walo + (size_t)(HDq + HDkv) * Cdim; }
    else                    { rel = bid - PREP_WV; W = Wo; N = Cdim;
                              Thi = nullptr; Tlo = nullptr; is_half = true; }

    const int ntiles = N / 32;
    int n0 = (rel % ntiles) * 32, k0 = (rel / ntiles) * 32;
    int tx = threadIdx.x & 31, ty = threadIdx.x >> 5;
#pragma unroll
    for (int j = 0; j < 4; j++)
        tile[ty + 8 * j][tx] = W[(size_t)(k0 + ty + 8 * j) * N + n0 + tx];
    __syncthreads();
#pragma unroll
    for (int j = 0; j < 4; j++) {
        int n = ty + 8 * j;
        float v = tile[tx][n];
        size_t o = (size_t)(n0 + n) * Cdim + k0 + tx;
        if (is_half) {
            g_wohi[o] = __float2half(v);
        } else {
            __nv_bfloat16 h = __float2bfloat16(v);
            Thi[o] = h;
            Tlo[o] = __float2bfloat16(v - __bfloat162float(h));
        }
    }
}

// ---------------- GEMM common geometry ----------------
#define PITCH   80
#define T_A     10240                  // 128 rows * 80B

// ---------------- bf16 3-MMA GEMM: C = A(hi/lo) * B(hi/lo)^T ----------------
#define T_STAGE (4 * T_A)
#define G_SMEM  (2 * T_STAGE)          // 81920

__device__ __forceinline__ void g_load_pair(
    uint32_t sbase, const __nv_bfloat16* __restrict__ hi,
    const __nv_bfloat16* __restrict__ lo, int rbase, int kc, int K, int tid)
{
#pragma unroll
    for (int i = 0; i < 2; i++) {
        int s = tid + 256 * i;
        int row = s >> 2, part = s & 3;
        size_t go = (size_t)(rbase + row) * K + (size_t)kc * 32 + part * 8;
        uint32_t so = (uint32_t)(row * PITCH + part * 16);
        CP_ASYNC16(sbase + so, hi + go);
        CP_ASYNC16(sbase + T_A + so, lo + go);
    }
}

__global__ void __launch_bounds__(256, 2) tcgemm_kernel(
    const __nv_bfloat16* __restrict__ Ahi, const __nv_bfloat16* __restrict__ Alo,
    const __nv_bfloat16* __restrict__ Bhi, const __nv_bfloat16* __restrict__ Blo,
    float* __restrict__ C, int N, int K)
{
    extern __shared__ char smc[];
    const uint32_t sb0 = smem_u32(smc);
    const int tid  = threadIdx.x;
    const int lane = tid & 31;
    const int wid  = tid >> 5;
    const int wm   = wid & 1;
    const int wn   = wid >> 1;
    const int row0 = blockIdx.y * 128;
    const int col0 = blockIdx.x * 128;

    float acc[4][4][4];
#pragma unroll
    for (int m = 0; m < 4; m++)
#pragma unroll
        for (int n = 0; n < 4; n++)
#pragma unroll
            for (int e = 0; e < 4; e++) acc[m][n][e] = 0.f;

    const uint32_t a_row = (uint32_t)(wm * 64 + (lane & 15));
    const uint32_t a_kb  = (uint32_t)((lane >> 4) * 16);
    const int bmat = lane >> 3, bwin = lane & 7;
    const uint32_t b_n  = (uint32_t)(wn * 32 + bwin + (bmat >> 1) * 8);
    const uint32_t b_kb = (uint32_t)((bmat & 1) * 16);

    const int nk = K >> 5;

    g_load_pair(sb0,           Ahi, Alo, row0, 0, K, tid);
    g_load_pair(sb0 + 2 * T_A, Bhi, Blo, col0, 0, K, tid);
    CP_COMMIT();

    for (int kc = 0; kc < nk; kc++) {
        uint32_t sb = sb0 + (uint32_t)(kc & 1) * T_STAGE;
        if (kc + 1 < nk) {
            uint32_t sb2 = sb0 + (uint32_t)((kc + 1) & 1) * T_STAGE;
            g_load_pair(sb2,           Ahi, Alo, row0, kc + 1, K, tid);
            g_load_pair(sb2 + 2 * T_A, Bhi, Blo, col0, kc + 1, K, tid);
            CP_COMMIT();
            CP_WAIT(1);
        } else {
            CP_WAIT(0);
        }
        __syncthreads();

        const uint32_t aB = sb + a_row * PITCH + a_kb;
        const uint32_t bB = sb + 2 * T_A + b_n * PITCH + b_kb;

#pragma unroll
        for (int ks = 0; ks < 2; ks++) {
            uint32_t ah[4][4], al[4][4], bh[2][4], bl[2][4];
#pragma unroll
            for (int m = 0; m < 4; m++) {
                ldsm4(ah[m], aB + (uint32_t)(m * 16 * PITCH) + ks * 32);
                ldsm4(al[m], aB + T_A + (uint32_t)(m * 16 * PITCH) + ks * 32);
            }
#pragma unroll
            for (int p = 0; p < 2; p++) {
                ldsm4(bh[p], bB + (uint32_t)(p * 16 * PITCH) + ks * 32);
                ldsm4(bl[p], bB + T_A + (uint32_t)(p * 16 * PITCH) + ks * 32);
            }
#pragma unroll
            for (int m = 0; m < 4; m++)
#pragma unroll
                for (int p = 0; p < 2; p++)
#pragma unroll
                    for (int h = 0; h < 2; h++) {
                        float* c = acc[m][p * 2 + h];
                        uint32_t bhh[2] = {bh[p][h * 2], bh[p][h * 2 + 1]};
                        uint32_t bll[2] = {bl[p][h * 2], bl[p][h * 2 + 1]};
                        mma_bf16(c, ah[m], bhh);
                        mma_bf16(c, ah[m], bll);
                        mma_bf16(c, al[m], bhh);
                    }
        }
        __syncthreads();
    }

    const int g = lane >> 2, t = lane & 3;
#pragma unroll
    for (int m = 0; m < 4; m++) {
        int r0 = row0 + wm * 64 + m * 16 + g;
#pragma unroll
        for (int n = 0; n < 4; n++) {
            int c = col0 + wn * 32 + n * 8 + 2 * t;
            *(float2*)&C[(size_t)r0 * N + c] = make_float2(acc[m][n][0], acc[m][n][1]);
            *(float2*)&C[(size_t)(r0 + 8) * N + c] = make_float2(acc[m][n][2], acc[m][n][3]);
        }
    }
}

// ---------------- fp16 2-MMA GEMM: C = (Ahi+Alo) * Bhi^T ----------------
#define T2_STAGE (3 * T_A)             // Ah, Al, Bh
#define G2_SMEM  (2 * T2_STAGE)        // 61440

__global__ void __launch_bounds__(256, 2) tcgemm2_kernel(
    const __half* __restrict__ Ahi, const __half* __restrict__ Alo,
    const __half* __restrict__ Bhi,
    float* __restrict__ C, int N, int K)
{
    extern __shared__ char smc[];
    const uint32_t sb0 = smem_u32(smc);
    const int tid  = threadIdx.x;
    const int lane = tid & 31;
    const int wid  = tid >> 5;
    const int wm   = wid & 1;
    const int wn   = wid >> 1;
    const int row0 = blockIdx.y * 128;
    const int col0 = blockIdx.x * 128;

    float acc[4][4][4];
#pragma unroll
    for (int m = 0; m < 4; m++)
#pragma unroll
        for (int n = 0; n < 4; n++)
#pragma unroll
            for (int e = 0; e < 4; e++) acc[m][n][e] = 0.f;

    const uint32_t a_row = (uint32_t)(wm * 64 + (lane & 15));
    const uint32_t a_kb  = (uint32_t)((lane >> 4) * 16);
    const int bmat = lane >> 3, bwin = lane & 7;
    const uint32_t b_n  = (uint32_t)(wn * 32 + bwin + (bmat >> 1) * 8);
    const uint32_t b_kb = (uint32_t)((bmat & 1) * 16);

    const int nk = K >> 5;

    auto load_stage = [&](uint32_t sb, int kc) {
#pragma unroll
        for (int i = 0; i < 2; i++) {
            int s = tid + 256 * i;
            int row = s >> 2, part = s & 3;
            size_t goA = (size_t)(row0 + row) * K + (size_t)kc * 32 + part * 8;
            size_t goB = (size_t)(col0 + row) * K + (size_t)kc * 32 + part * 8;
            uint32_t so = (uint32_t)(row * PITCH + part * 16);
            CP_ASYNC16(sb + so,           Ahi + goA);
            CP_ASYNC16(sb + T_A + so,     Alo + goA);
            CP_ASYNC16(sb + 2 * T_A + so, Bhi + goB);
        }
    };

    load_stage(sb0, 0);
    CP_COMMIT();

    for (int kc = 0; kc < nk; kc++) {
        uint32_t sb = sb0 + (uint32_t)(kc & 1) * T2_STAGE;
        if (kc + 1 < nk) {
            load_stage(sb0 + (uint32_t)((kc + 1) & 1) * T2_STAGE, kc + 1);
            CP_COMMIT();
            CP_WAIT(1);
        } else {
            CP_WAIT(0);
        }
        __syncthreads();

        const uint32_t aB = sb + a_row * PITCH + a_kb;
        const uint32_t bB = sb + 2 * T_A + b_n * PITCH + b_kb;

#pragma unroll
        for (int ks = 0; ks < 2; ks++) {
            uint32_t ah[4][4], al[4][4], bh[2][4];
#pragma unroll
            for (int m = 0; m < 4; m++) {
                ldsm4(ah[m], aB + (uint32_t)(m * 16 * PITCH) + ks * 32);
                ldsm4(al[m], aB + T_A + (uint32_t)(m * 16 * PITCH) + ks * 32);
            }
#pragma unroll
            for (int p = 0; p < 2; p++)
                ldsm4(bh[p], bB + (uint32_t)(p * 16 * PITCH) + ks * 32);
#pragma unroll
            for (int m = 0; m < 4; m++)
#pragma unroll
                for (int p = 0; p < 2; p++)
#pragma unroll
                    for (int h = 0; h < 2; h++) {
                        float* c = acc[m][p * 2 + h];
                        uint32_t bhh[2] = {bh[p][h * 2], bh[p][h * 2 + 1]};
                        mma_f16(c, ah[m], bhh);
                        mma_f16(c, al[m], bhh);
                    }
        }
        __syncthreads();
    }

    const int g = lane >> 2, t = lane & 3;
#pragma unroll
    for (int m = 0; m < 4; m++) {
        int r0 = row0 + wm * 64 + m * 16 + g;
#pragma unroll
        for (int n = 0; n < 4; n++) {
            int c = col0 + wn * 32 + n * 8 + 2 * t;
            *(float2*)&C[(size_t)r0 * N + c] = make_float2(acc[m][n][0], acc[m][n][1]);
            *(float2*)&C[(size_t)(r0 + 8) * N + c] = make_float2(acc[m][n][2], acc[m][n][3]);
        }
    }
}

// ---------------- merged RoPE: q part + kv part in one launch ----------------
#define ROPE_QBLOCKS ((NH * Tn * 64) / 256)     // 16384
#define ROPE_KVBLOCKS ((NKV * Tn * 64) / 256)   // 4096

__global__ void __launch_bounds__(256) rope_all_kernel(
    const float* __restrict__ cosb, const float* __restrict__ sinb,
    float* __restrict__ outK, float* __restrict__ outV)
{
    int bid = blockIdx.x;
    if (bid < ROPE_QBLOCKS) {
        int idx = bid * 256 + threadIdx.x;
        int d = idx & 63;
        int t = (idx >> 6) & (Tn - 1);
        int h = idx >> 17;
        float u1 = g_tqkv[(size_t)t * HDA + h * Dh + d];
        float u2 = g_tqkv[(size_t)t * HDA + h * Dh + d + 64];
        float c1 = cosb[t * Dh + d],      s1 = sinb[t * Dh + d];
        float c2 = cosb[t * Dh + d + 64], s2 = sinb[t * Dh + d + 64];
        float y1 = u1 * c1 - u2 * s1;
        float y2 = u2 * c2 + u1 * s2;
        size_t o = ((size_t)h * Tn + t) * Dh + d;
        __nv_bfloat16 h1 = __float2bfloat16(y1), h2 = __float2bfloat16(y2);
        g_qhi[o]      = h1;
        g_qlo[o]      = __float2bfloat16(y1 - __bfloat162float(h1));
        g_qhi[o + 64] = h2;
        g_qlo[o + 64] = __float2bfloat16(y2 - __bfloat162float(h2));
    } else {
        int idx = (bid - ROPE_QBLOCKS) * 256 + threadIdx.x;
        int d  = idx & 63;
        int t  = (idx >> 6) & (Tn - 1);
        int kh = idx >> 17;
        float u1 = g_tqkv[(size_t)t * HDA + HDq + kh * Dh + d];
        float u2 = g_tqkv[(size_t)t * HDA + HDq + kh * Dh + d + 64];
        float c1 = cosb[t * Dh + d],      s1 = sinb[t * Dh + d];
        float c2 = cosb[t * Dh + d + 64], s2 = sinb[t * Dh + d + 64];
        float y1 = u1 * c1 - u2 * s1;
        float y2 = u2 * c2 + u1 * s2;
        size_t o = ((size_t)kh * Tn + t) * Dh + d;
        outK[o]      = y1;
        outK[o + 64] = y2;
        __nv_bfloat16 h1 = __float2bfloat16(y1), h2 = __float2bfloat16(y2);
        g_khi[o]      = h1;
        g_klo[o]      = __float2bfloat16(y1 - __bfloat162float(h1));
        g_khi[o + 64] = h2;
        g_klo[o + 64] = __float2bfloat16(y2 - __bfloat162float(h2));
        float v1 = g_tqkv[(size_t)t * HDA + HDq + HDkv + kh * Dh + d];
        float v2 = g_tqkv[(size_t)t * HDA + HDq + HDkv + kh * Dh + d + 64];
        outV[o]      = v1;
        outV[o + 64] = v2;
        g_vh[o]      = __float2half(v1);
        g_vh[o + 64] = __float2half(v2);
    }
}

// ---------------- flash attention (QK: bf16 3-MMA, PV: fp16 2-MMA) ----------------
// BM=128, BN=64. 8 warps, each owns 16 rows full width. grid (16, NH), 256 thr.
// 3-stage KV pipeline.
#define FP272   272
#define QTILE   (128 * FP272)          // 34816
#define KTILE   (64 * FP272)           // 17408
#define FSTAGE  (3 * KTILE)            // Kh, Kl, Vh = 52224
#define F_SMEM  (2 * QTILE + 3 * FSTAGE)  // 226304

__device__ __forceinline__ void f_load_kv(
    uint32_t st, const __nv_bfloat16* __restrict__ kh,
    const __nv_bfloat16* __restrict__ kl, const __half* __restrict__ vh, int tid)
{
#pragma unroll
    for (int i = 0; i < 4; i++) {
        int s = tid + 256 * i;             // 1024 chunks of 16B per tile
        int r = s >> 4, c = s & 15;
        uint32_t so = (uint32_t)(r * FP272 + c * 16);
        size_t go = (size_t)r * Dh + c * 8;
        CP_ASYNC16(st + so,             kh + go);
        CP_ASYNC16(st + KTILE + so,     kl + go);
        CP_ASYNC16(st + 2 * KTILE + so, vh + go);
    }
}

__global__ void __launch_bounds__(256) flash_mma_kernel(
    __half* __restrict__ ybhi, __half* __restrict__ yblo)
{
    extern __shared__ char smc[];
    const uint32_t sb = smem_u32(smc);
    const int tid = threadIdx.x, lane = tid & 31, w = tid >> 5;
    const int h  = blockIdx.y;
    const int qi = (int)gridDim.x - 1 - (int)blockIdx.x;   // big tiles first
    const int q0 = qi * 128;
    const int kvh = h >> 2;
    const int nb = 2 * qi + 2;

    const uint32_t sQh = sb, sQl = sb + QTILE;
    const uint32_t sKV = sb + 2 * QTILE;

    const uint32_t aQoff = (uint32_t)((16 * w + (lane & 15)) * FP272 + (lane >> 4) * 16);
    const int bmat = lane >> 3, bwin = lane & 7;
    const uint32_t bKoff = (uint32_t)((bwin + ((bmat >> 1) << 3)) * FP272 + ((bmat & 1) << 4));
    const uint32_t bVoff = (uint32_t)((lane & 15) * FP272 + ((lane >> 4) << 4));

    const __nv_bfloat16* gKh = g_khi + (size_t)kvh * Tn * Dh;
    const __nv_bfloat16* gKl = g_klo + (size_t)kvh * Tn * Dh;
    const __half*        gVh = g_vh  + (size_t)kvh * Tn * Dh;

    // prologue: Q + KV0 (group 0), KV1 (group 1; nb >= 2 always)
    {
        const __nv_bfloat16* gqh = g_qhi + ((size_t)h * Tn + q0) * Dh;
        const __nv_bfloat16* gql = g_qlo + ((size_t)h * Tn + q0) * Dh;
#pragma unroll
        for (int i = 0; i < 8; i++) {
            int s = tid + 256 * i;
            int r = s >> 4, c = s & 15;
            uint32_t so = (uint32_t)(r * FP272 + c * 16);
            size_t go = (size_t)r * Dh + c * 8;
            CP_ASYNC16(sQh + so, gqh + go);
            CP_ASYNC16(sQl + so, gql + go);
        }
        f_load_kv(sKV, gKh, gKl, gVh, tid);
        CP_COMMIT();
        f_load_kv(sKV + FSTAGE, gKh + (size_t)64 * Dh, gKl + (size_t)64 * Dh,
                  gVh + (size_t)64 * Dh, tid);
        CP_COMMIT();
    }

    CP_WAIT(1);
    __syncthreads();
    uint32_t qh_f[8][4], ql_f[8][4];
#pragma unroll
    for (int ks = 0; ks < 8; ks++) {
        ldsm4(qh_f[ks], sQh + aQoff + ks * 32);
        ldsm4(ql_f[ks], sQl + aQoff + ks * 32);
    }

    float o[16][4];
#pragma unroll
    for (int dt = 0; dt < 16; dt++)
#pragma unroll
        for (int e = 0; e < 4; e++) o[dt][e] = 0.f;
    float m0 = -1e30f, m1 = -1e30f, l0 = 0.f, l1 = 0.f;

    const int row_lo = q0 + 16 * w + (lane >> 2);
    const int row_hi = row_lo + 8;

    for (int j = 0; j < nb; j++) {
        if (j > 0) {
            if (j + 1 < nb) CP_WAIT(1); else CP_WAIT(0);
            __syncthreads();
        }
        if (j + 2 < nb) {
            size_t kb = (size_t)(j + 2) * 64;
            f_load_kv(sKV + (uint32_t)((j + 2) % 3) * FSTAGE,
                      gKh + kb * Dh, gKl + kb * Dh, gVh + kb * Dh, tid);
            CP_COMMIT();
        }

        const uint32_t stg = sKV + (uint32_t)(j % 3) * FSTAGE;
        const int kb0 = j * 64;
        const bool active = (q0 + 16 * w + 15) >= kb0;

        if (active) {
            float sc[8][4];
#pragma unroll
            for (int nt = 0; nt < 8; nt++)
#pragma unroll
                for (int e = 0; e < 4; e++) sc[nt][e] = 0.f;

#pragma unroll
            for (int ks = 0; ks < 8; ks++) {
#pragma unroll
                for (int p = 0; p < 4; p++) {
                    uint32_t khf[4], klf[4];
                    uint32_t ka = stg + bKoff + (uint32_t)(p * 16 * FP272) + ks * 32;
                    ldsm4(khf, ka);
                    ldsm4(klf, ka + KTILE);
#pragma unroll
                    for (int hh = 0; hh < 2; hh++) {
                        float* c = sc[p * 2 + hh];
                        uint32_t bh2[2] = {khf[hh * 2], khf[hh * 2 + 1]};
                        uint32_t bl2[2] = {klf[hh * 2], klf[hh * 2 + 1]};
                        mma_bf16(c, qh_f[ks], bh2);
                        mma_bf16(c, qh_f[ks], bl2);
                        mma_bf16(c, ql_f[ks], bh2);
                    }
                }
            }

            if (kb0 + 63 > row_lo) {
#pragma unroll
                for (int nt = 0; nt < 8; nt++) {
                    int col = kb0 + nt * 8 + 2 * (lane & 3);
                    if (col > row_lo)     sc[nt][0] = -1e30f;
                    if (col + 1 > row_lo) sc[nt][1] = -1e30f;
                    if (col > row_hi)     sc[nt][2] = -1e30f;
                    if (col + 1 > row_hi) sc[nt][3] = -1e30f;
                }
            }

            float ml0 = -1e30f, ml1 = -1e30f;
#pragma unroll
            for (int nt = 0; nt < 8; nt++) {
                ml0 = fmaxf(ml0, fmaxf(sc[nt][0], sc[nt][1]));
                ml1 = fmaxf(ml1, fmaxf(sc[nt][2], sc[nt][3]));
            }
            ml0 = fmaxf(ml0, __shfl_xor_sync(0xffffffffu, ml0, 1));
            ml0 = fmaxf(ml0, __shfl_xor_sync(0xffffffffu, ml0, 2));
            ml1 = fmaxf(ml1, __shfl_xor_sync(0xffffffffu, ml1, 1));
            ml1 = fmaxf(ml1, __shfl_xor_sync(0xffffffffu, ml1, 2));
            float mn0 = fmaxf(m0, ml0), mn1 = fmaxf(m1, ml1);
            float es0 = __expf(m0 - mn0), es1 = __expf(m1 - mn1);
            float ls0 = 0.f, ls1 = 0.f;
#pragma unroll
            for (int nt = 0; nt < 8; nt++) {
                sc[nt][0] = __expf(sc[nt][0] - mn0);
                sc[nt][1] = __expf(sc[nt][1] - mn0);
                sc[nt][2] = __expf(sc[nt][2] - mn1);
                sc[nt][3] = __expf(sc[nt][3] - mn1);
                ls0 += sc[nt][0] + sc[nt][1];
                ls1 += sc[nt][2] + sc[nt][3];
            }
            ls0 += __shfl_xor_sync(0xffffffffu, ls0, 1);
            ls0 += __shfl_xor_sync(0xffffffffu, ls0, 2);
            ls1 += __shfl_xor_sync(0xffffffffu, ls1, 1);
            ls1 += __shfl_xor_sync(0xffffffffu, ls1, 2);
            l0 = l0 * es0 + ls0;  m0 = mn0;
            l1 = l1 * es1 + ls1;  m1 = mn1;
#pragma unroll
            for (int dt = 0; dt < 16; dt++) {
                o[dt][0] *= es0;  o[dt][1] *= es0;
                o[dt][2] *= es1;  o[dt][3] *= es1;
            }

#pragma unroll
            for (int j2 = 0; j2 < 4; j2++) {
                uint32_t ph[4], pl[4];
                split2h(sc[2 * j2][0],     sc[2 * j2][1],     ph[0], pl[0]);
                split2h(sc[2 * j2][2],     sc[2 * j2][3],     ph[1], pl[1]);
                split2h(sc[2 * j2 + 1][0], sc[2 * j2 + 1][1], ph[2], pl[2]);
                split2h(sc[2 * j2 + 1][2], sc[2 * j2 + 1][3], ph[3], pl[3]);
#pragma unroll
                for (int dt2 = 0; dt2 < 8; dt2++) {
                    uint32_t vhf[4];
                    uint32_t va = stg + 2 * KTILE + bVoff +
                                  (uint32_t)(j2 * 16 * FP272) + (uint32_t)(dt2 * 32);
                    ldsm4t(vhf, va);
#pragma unroll
                    for (int hf = 0; hf < 2; hf++) {
                        float* c = o[dt2 * 2 + hf];
                        uint32_t bh2[2] = {vhf[hf * 2], vhf[hf * 2 + 1]};
                        mma_f16(c, ph, bh2);
                        mma_f16(c, pl, bh2);
                    }
                }
            }
        }
    }

    float inv0 = 1.f / l0, inv1 = 1.f / l1;
#pragma unroll
    for (int dt = 0; dt < 16; dt++) {
        int d = dt * 8 + 2 * (lane & 3);
        size_t o0 = (size_t)row_lo * Cdim + h * Dh + d;
        size_t o1 = (size_t)row_hi * Cdim + h * Dh + d;
        uint32_t hi0, lo0, hi1, lo1;
        split2h(o[dt][0] * inv0, o[dt][1] * inv0, hi0, lo0);
        split2h(o[dt][2] * inv1, o[dt][3] * inv1, hi1, lo1);
        *reinterpret_cast<uint32_t*>(ybhi + o0) = hi0;
        *reinterpret_cast<uint32_t*>(yblo + o0) = lo0;
        *reinterpret_cast<uint32_t*>(ybhi + o1) = hi1;
        *reinterpret_cast<uint32_t*>(yblo + o1) = lo1;
    }
}

// ---------------- launch ----------------
extern "C" void kernel_launch(void* const* d_in, const int* in_sizes, int n_in,
                              void* d_out, int out_size)
{
    const float* x    = (const float*)d_in[0];
    const float* Wq   = (const float*)d_in[1];
    const float* Wk   = (const float*)d_in[2];
    const float* Wv   = (const float*)d_in[3];
    const float* Wo   = (const float*)d_in[4];
    const float* cosb = (const float*)d_in[5];
    const float* sinb = (const float*)d_in[6];
    // d_in[7] = mask (reproduced exactly by causal structure; unused)

    float* out  = (float*)d_out;
    float* outY = out;
    float* outK = out + (size_t)Tn * Cdim;
    float* outV = outK + (size_t)NKV * Tn * Dh;

    float* tqkv;
    cudaGetSymbolAddress((void**)&tqkv, g_tqkv);
    __nv_bfloat16 *xhi, *xlo, *wahi, *walo;
    __half *ybhi, *yblo, *wohi;
    cudaGetSymbolAddress((void**)&xhi, g_xhi);
    cudaGetSymbolAddress((void**)&xlo, g_xlo);
    cudaGetSymbolAddress((void**)&wahi, g_wahi);
    cudaGetSymbolAddress((void**)&walo, g_walo);
    cudaGetSymbolAddress((void**)&ybhi, g_ybhi);
    cudaGetSymbolAddress((void**)&yblo, g_yblo);
    cudaGetSymbolAddress((void**)&wohi, g_wohi);

    cudaFuncSetAttribute(tcgemm_kernel, cudaFuncAttributeMaxDynamicSharedMemorySize,
                         G_SMEM);
    cudaFuncSetAttribute(tcgemm2_kernel, cudaFuncAttributeMaxDynamicSharedMemorySize,
                         G2_SMEM);
    cudaFuncSetAttribute(flash_mma_kernel, cudaFuncAttributeMaxDynamicSharedMemorySize,
                         F_SMEM);

    // 0. merged prep: x split + all weight transposes (ONE launch)
    prep_kernel<<<PREP_END, 256>>>(x, Wq, Wk, Wv, Wo);

    // 1. merged QKV projection (bf16 3-MMA, one launch, N=6144)
    tcgemm_kernel<<<dim3(HDA / 128, Tn / 128), 256, G_SMEM>>>(
        xhi, xlo, wahi, walo, tqkv, HDA, Cdim);

    // 2. merged RoPE + plane conversion (k/v fp32 copies are final outputs)
    rope_all_kernel<<<ROPE_QBLOCKS + ROPE_KVBLOCKS, 256>>>(cosb, sinb, outK, outV);

    // 3. causal flash attention (tensor cores, 3-stage KV pipeline)
    flash_mma_kernel<<<dim3(Tn / 128, NH), 256, F_SMEM>>>(ybhi, yblo);

    // 4. output projection (fp16 2-MMA)
    tcgemm2_kernel<<<dim3(Cdim / 128, Tn / 128), 256, G2_SMEM>>>(
        ybhi, yblo, wohi, outY, Cdim, Cdim);
}